// round 17
// baseline (speedup 1.0000x reference)
#include <cuda_runtime.h>
#include <cuda_bf16.h>
#include <cuda_fp16.h>
#include <cstdint>

// ---------------------------------------------------------------------------
// Spconv (9-tap rulebook) + LeakyReLU + BatchNorm1d via split-precision
// bf16 HMMA (3-term) with fp16 y-staging, fully fused:
//   launch 1 (k_prep): mask-dtype detect + BN zero + B-fragment build + ctr
//   launch 2 (k_conv): persistent conv -> device-wide barrier -> normalize
// R17 = R16 with launch-overhead collapsed (2 launches instead of 5).
// ---------------------------------------------------------------------------

#define FULLMASK 0xffffffffu
#define NEG_SLOPE 0.01f
#define BN_EPS 1e-5f
#define PERSIST_CTAS 296
#define Y_CAP_VOX 1048576            // scratch capacity in voxels

__device__ int      g_mask_mode;   // 0 = float32, 1 = int32, 2 = uint8/bool
__device__ double   g_sum[32];
__device__ double   g_sumsq[32];
__device__ unsigned g_done;        // completion counter for device barrier
__device__ __half2  g_y[(size_t)Y_CAP_VOX * 16];   // 64 MB fp16 y scratch
// B fragments: frag fi = ((tap*4 + chunk)*4 + nfrag), per lane two u32 regs.
__device__ uint32_t g_wb0[9 * 4 * 4 * 32];
__device__ uint32_t g_wb1[9 * 4 * 4 * 32];

__device__ __forceinline__ uint32_t hi2(float e0, float e1) {
    uint32_t r;
    asm("cvt.rn.bf16x2.f32 %0, %1, %2;" : "=r"(r) : "f"(e1), "f"(e0));
    return r;
}
__device__ __forceinline__ uint32_t lo2(uint32_t h, float e0, float e1) {
    float h0 = __uint_as_float(h << 16);
    float h1 = __uint_as_float(h & 0xffff0000u);
    return hi2(e0 - h0, e1 - h1);
}

__device__ __forceinline__ void mma_bf16(float* d, const uint32_t* a,
                                         uint32_t b0, uint32_t b1) {
    asm volatile(
        "mma.sync.aligned.m16n8k16.row.col.f32.bf16.bf16.f32 "
        "{%0,%1,%2,%3}, {%4,%5,%6,%7}, {%8,%9}, {%0,%1,%2,%3};"
        : "+f"(d[0]), "+f"(d[1]), "+f"(d[2]), "+f"(d[3])
        : "r"(a[0]), "r"(a[1]), "r"(a[2]), "r"(a[3]), "r"(b0), "r"(b1));
}

__device__ __forceinline__ void gather_rows4(const float* __restrict__ feat,
                                             int jA, int jB, int c4,
                                             float4* p) {
    const float4 z = make_float4(0.f, 0.f, 0.f, 0.f);
    p[0] = z; p[1] = z; p[2] = z; p[3] = z;
    if (jA >= 0) {
        const float4* f = (const float4*)(feat + (size_t)jA * 32);
        p[0] = f[c4]; p[2] = f[c4 + 4];
    }
    if (jB >= 0) {
        const float4* f = (const float4*)(feat + (size_t)jB * 32);
        p[1] = f[c4]; p[3] = f[c4 + 4];
    }
}

// ---------------------------------------------------------------------------
// K_prep: mask dtype detect + BN zero + barrier reset + B-fragment build.
// One block, 256 threads.
// ---------------------------------------------------------------------------
__global__ void k_prep(const unsigned int* __restrict__ mask_words,
                       const float* __restrict__ wt) {
    __shared__ int s_f32, s_u8;
    const int t = threadIdx.x;
    if (t == 0) { s_f32 = 0; s_u8 = 0; g_done = 0u; }
    if (t < 32) { g_sum[t] = 0.0; g_sumsq[t] = 0.0; }
    __syncthreads();
    if (t < 64) {
        int f32 = 0, u8 = 0;
#pragma unroll
        for (int i = 0; i < 4; i++) {
            unsigned w = mask_words[t * 4 + i];
            if (w == 0x3F800000u) f32 = 1;
            else if (w & 0xFFFFFF00u) u8 = 1;
        }
        if (f32) atomicOr(&s_f32, 1);
        if (u8)  atomicOr(&s_u8, 1);
    }
    __syncthreads();
    if (t == 0) g_mask_mode = s_f32 ? 0 : (s_u8 ? 2 : 1);

    // B fragments with k-permutation (validated R12)
    for (int e = t; e < 9 * 4 * 4 * 32; e += blockDim.x) {
        int lane = e & 31;
        int fi   = e >> 5;
        int nf   = fi & 3;
        int j    = (fi >> 2) & 3;
        int tap  = fi >> 4;
        int n    = nf * 8 + (lane >> 2);
        int q    = lane & 3;
        int o    = (j & 1) * 16;
        float w0 = wt[(tap * 32 + 4 * q + 0 + o) * 32 + n];
        float w1 = wt[(tap * 32 + 4 * q + 1 + o) * 32 + n];
        float w8 = wt[(tap * 32 + 4 * q + 2 + o) * 32 + n];
        float w9 = wt[(tap * 32 + 4 * q + 3 + o) * 32 + n];
        uint32_t r0, r1;
        if (j < 2) {
            r0 = hi2(w0, w1);
            r1 = hi2(w8, w9);
        } else {
            uint32_t h0 = hi2(w0, w1), h1 = hi2(w8, w9);
            r0 = lo2(h0, w0, w1);
            r1 = lo2(h1, w8, w9);
        }
        g_wb0[e] = r0;
        g_wb1[e] = r1;
    }
}

// ---------------------------------------------------------------------------
// K1 (persistent, fused): tile loop (gather -> bf16 HMMA -> LeakyReLU ->
// fp16 y + BN partials) -> device barrier -> BN finalize -> normalize.
// ---------------------------------------------------------------------------
__global__ void __launch_bounds__(256, 2) k_conv(
    const float* __restrict__ feat,   // [N,32]
    const int*   __restrict__ nidx,   // [9,N]
    const void*  __restrict__ nmask,  // [9,N]
    float* __restrict__ out,          // [N,32]
    const float* __restrict__ gamma,
    const float* __restrict__ beta,
    int N, int tiles, int use16, int nctas)
{
    __shared__ uint32_t wb0_s[9 * 4 * 4 * 32];
    __shared__ uint32_t wb1_s[9 * 4 * 4 * 32];
    __shared__ int      j_s[9][256];
    __shared__ double   s_sum[32];
    __shared__ double   s_sumsq[32];
    __shared__ float    sc[32], bi[32];

    const int tid  = threadIdx.x;
    const int mode = g_mask_mode;
    const size_t Ns = (size_t)N;

    for (int i = tid; i < 1152; i += 256) {
        ((uint4*)wb0_s)[i] = ((const uint4*)g_wb0)[i];
        ((uint4*)wb1_s)[i] = ((const uint4*)g_wb1)[i];
    }
    if (tid < 32) { s_sum[tid] = 0.0; s_sumsq[tid] = 0.0; }

    const int wid   = tid >> 5;
    const int lane  = tid & 31;
    const int woff  = wid * 32;
    const int qrow  = lane >> 2;
    const int c4    = lane & 3;
    const int cbase = (lane & 3) * 2;

    for (int tb = blockIdx.x; tb < tiles; tb += gridDim.x) {
        const int tile = tb * 256;

        __syncthreads();
        {
            const int g = tile + tid;
            const bool v = (g < N);
            if (mode == 0) {
                const float* mp = (const float*)nmask;
#pragma unroll
                for (int k = 0; k < 9; k++) {
                    const size_t kb = (size_t)k * Ns;
                    int idx = v ? nidx[kb + g] : 0;
                    j_s[k][tid] = (v && mp[kb + g] != 0.0f) ? idx : -1;
                }
            } else if (mode == 1) {
                const int* mp = (const int*)nmask;
#pragma unroll
                for (int k = 0; k < 9; k++) {
                    const size_t kb = (size_t)k * Ns;
                    int idx = v ? nidx[kb + g] : 0;
                    j_s[k][tid] = (v && mp[kb + g] != 0) ? idx : -1;
                }
            } else {
                const unsigned char* mp = (const unsigned char*)nmask;
#pragma unroll
                for (int k = 0; k < 9; k++) {
                    const size_t kb = (size_t)k * Ns;
                    int idx = v ? nidx[kb + g] : 0;
                    j_s[k][tid] = (v && mp[kb + g] != 0) ? idx : -1;
                }
            }
        }
        __syncthreads();

        const int r0g = tile + woff + qrow;
        const int r1g = r0g + 8;
        const int r2g = r0g + 16;
        const int r3g = r0g + 24;
        const bool v0 = (r0g < N), v1 = (r1g < N), v2 = (r2g < N), v3 = (r3g < N);

        float acc0[4][4], acc1[4][4];
#pragma unroll
        for (int nf = 0; nf < 4; nf++)
#pragma unroll
            for (int i = 0; i < 4; i++) { acc0[nf][i] = 0.0f; acc1[nf][i] = 0.0f; }

        float4 rawA[4], rawB[4];
        {
            int j0 = j_s[0][woff + qrow];
            int j1 = j_s[0][woff + qrow + 8];
            int j2 = j_s[0][woff + qrow + 16];
            int j3 = j_s[0][woff + qrow + 24];
            gather_rows4(feat, j0, j1, c4, rawA);
            gather_rows4(feat, j2, j3, c4, rawB);
        }

#pragma unroll
        for (int k = 0; k < 9; k++) {
            uint32_t A0hi0[4], A0hi1[4], A0lo0[4], A0lo1[4];
            uint32_t A1hi0[4], A1hi1[4], A1lo0[4], A1lo1[4];
#pragma unroll
            for (int i = 0; i < 2; i++) {
                A0hi0[i]     = hi2(rawA[i].x, rawA[i].y);
                A0lo0[i]     = lo2(A0hi0[i], rawA[i].x, rawA[i].y);
                A0hi0[i + 2] = hi2(rawA[i].z, rawA[i].w);
                A0lo0[i + 2] = lo2(A0hi0[i + 2], rawA[i].z, rawA[i].w);
                A0hi1[i]     = hi2(rawA[i + 2].x, rawA[i + 2].y);
                A0lo1[i]     = lo2(A0hi1[i], rawA[i + 2].x, rawA[i + 2].y);
                A0hi1[i + 2] = hi2(rawA[i + 2].z, rawA[i + 2].w);
                A0lo1[i + 2] = lo2(A0hi1[i + 2], rawA[i + 2].z, rawA[i + 2].w);
                A1hi0[i]     = hi2(rawB[i].x, rawB[i].y);
                A1lo0[i]     = lo2(A1hi0[i], rawB[i].x, rawB[i].y);
                A1hi0[i + 2] = hi2(rawB[i].z, rawB[i].w);
                A1lo0[i + 2] = lo2(A1hi0[i + 2], rawB[i].z, rawB[i].w);
                A1hi1[i]     = hi2(rawB[i + 2].x, rawB[i + 2].y);
                A1lo1[i]     = lo2(A1hi1[i], rawB[i + 2].x, rawB[i + 2].y);
                A1hi1[i + 2] = hi2(rawB[i + 2].z, rawB[i + 2].w);
                A1lo1[i + 2] = lo2(A1hi1[i + 2], rawB[i + 2].z, rawB[i + 2].w);
            }

            if (k < 8) {
                int j0 = j_s[k + 1][woff + qrow];
                int j1 = j_s[k + 1][woff + qrow + 8];
                int j2 = j_s[k + 1][woff + qrow + 16];
                int j3 = j_s[k + 1][woff + qrow + 24];
                gather_rows4(feat, j0, j1, c4, rawA);
                gather_rows4(feat, j2, j3, c4, rawB);
            }

            const int fb = k * 16;
#pragma unroll
            for (int nf = 0; nf < 4; nf++) {
                const int i0x = (fb + 0 * 4 + nf) * 32 + lane;
                const int i1x = (fb + 1 * 4 + nf) * 32 + lane;
                const int i2x = (fb + 2 * 4 + nf) * 32 + lane;
                const int i3x = (fb + 3 * 4 + nf) * 32 + lane;
                const uint32_t bh00 = wb0_s[i0x], bh01 = wb1_s[i0x];
                const uint32_t bh10 = wb0_s[i1x], bh11 = wb1_s[i1x];
                const uint32_t bl00 = wb0_s[i2x], bl01 = wb1_s[i2x];
                const uint32_t bl10 = wb0_s[i3x], bl11 = wb1_s[i3x];
                mma_bf16(acc0[nf], A0hi0, bh00, bh01);
                mma_bf16(acc1[nf], A1hi0, bh00, bh01);
                mma_bf16(acc0[nf], A0hi1, bh10, bh11);
                mma_bf16(acc1[nf], A1hi1, bh10, bh11);
                mma_bf16(acc0[nf], A0lo0, bh00, bh01);
                mma_bf16(acc1[nf], A1lo0, bh00, bh01);
                mma_bf16(acc0[nf], A0lo1, bh10, bh11);
                mma_bf16(acc1[nf], A1lo1, bh10, bh11);
                mma_bf16(acc0[nf], A0hi0, bl00, bl01);
                mma_bf16(acc1[nf], A1hi0, bl00, bl01);
                mma_bf16(acc0[nf], A0hi1, bl10, bl11);
                mma_bf16(acc1[nf], A1hi1, bl10, bl11);
            }
        }

        // ---- LeakyReLU + y store + BN partials ----
        float s8[8], z8[8];
#pragma unroll
        for (int i = 0; i < 8; i++) { s8[i] = 0.0f; z8[i] = 0.0f; }

#pragma unroll
        for (int nf = 0; nf < 4; nf++) {
            float a0 = acc0[nf][0], a1 = acc0[nf][1];
            float a2 = acc0[nf][2], a3 = acc0[nf][3];
            float b0 = acc1[nf][0], b1 = acc1[nf][1];
            float b2 = acc1[nf][2], b3 = acc1[nf][3];
            a0 = (a0 >= 0.0f) ? a0 : NEG_SLOPE * a0;
            a1 = (a1 >= 0.0f) ? a1 : NEG_SLOPE * a1;
            a2 = (a2 >= 0.0f) ? a2 : NEG_SLOPE * a2;
            a3 = (a3 >= 0.0f) ? a3 : NEG_SLOPE * a3;
            b0 = (b0 >= 0.0f) ? b0 : NEG_SLOPE * b0;
            b1 = (b1 >= 0.0f) ? b1 : NEG_SLOPE * b1;
            b2 = (b2 >= 0.0f) ? b2 : NEG_SLOPE * b2;
            b3 = (b3 >= 0.0f) ? b3 : NEG_SLOPE * b3;
            if (use16) {
                const int pr = nf * 4 + c4;
                if (v0) g_y[(size_t)r0g * 16 + pr] = __floats2half2_rn(a0, a1);
                if (v1) g_y[(size_t)r1g * 16 + pr] = __floats2half2_rn(a2, a3);
                if (v2) g_y[(size_t)r2g * 16 + pr] = __floats2half2_rn(b0, b1);
                if (v3) g_y[(size_t)r3g * 16 + pr] = __floats2half2_rn(b2, b3);
            } else {
                const int col = nf * 8 + cbase;
                if (v0) *(float2*)(out + (size_t)r0g * 32 + col) = make_float2(a0, a1);
                if (v1) *(float2*)(out + (size_t)r1g * 32 + col) = make_float2(a2, a3);
                if (v2) *(float2*)(out + (size_t)r2g * 32 + col) = make_float2(b0, b1);
                if (v3) *(float2*)(out + (size_t)r3g * 32 + col) = make_float2(b2, b3);
            }
            if (!v0) { a0 = 0.0f; a1 = 0.0f; }
            if (!v1) { a2 = 0.0f; a3 = 0.0f; }
            if (!v2) { b0 = 0.0f; b1 = 0.0f; }
            if (!v3) { b2 = 0.0f; b3 = 0.0f; }
            s8[nf * 2 + 0] = a0 + a2 + b0 + b2;
            s8[nf * 2 + 1] = a1 + a3 + b1 + b3;
            z8[nf * 2 + 0] = a0 * a0 + a2 * a2 + b0 * b0 + b2 * b2;
            z8[nf * 2 + 1] = a1 * a1 + a3 * a3 + b1 * b1 + b3 * b3;
        }

#pragma unroll
        for (int off = 4; off < 32; off <<= 1) {
#pragma unroll
            for (int i = 0; i < 8; i++) {
                s8[i] += __shfl_xor_sync(FULLMASK, s8[i], off);
                z8[i] += __shfl_xor_sync(FULLMASK, z8[i], off);
            }
        }
        if (lane < 4) {
#pragma unroll
            for (int i = 0; i < 8; i++) {
                const int ch = (i >> 1) * 8 + (lane * 2) + (i & 1);
                atomicAdd(&s_sum[ch],   (double)s8[i]);
                atomicAdd(&s_sumsq[ch], (double)z8[i]);
            }
        }
    }

    // ---- flush BN partials, then device-wide completion barrier ----
    __syncthreads();
    if (tid < 32) {
        atomicAdd(&g_sum[tid],   s_sum[tid]);
        atomicAdd(&g_sumsq[tid], s_sumsq[tid]);
    }
    __threadfence();
    __syncthreads();
    if (tid == 0) {
        atomicAdd(&g_done, 1u);
        while (atomicAdd(&g_done, 0u) < (unsigned)nctas) { }
    }
    __syncthreads();

    // ---- BN finalize (L1-bypassing reads via atomic add of 0) ----
    if (tid < 32) {
        double sv = atomicAdd(&g_sum[tid],   0.0);
        double zv = atomicAdd(&g_sumsq[tid], 0.0);
        double invN = 1.0 / (double)N;
        double mean = sv * invN;
        double var  = zv * invN - mean * mean;
        float s = gamma[tid] * rsqrtf((float)var + BN_EPS);
        sc[tid] = s;
        bi[tid] = beta[tid] - (float)mean * s;
    }
    __syncthreads();

    // ---- normalize: grid-strided ----
    if (use16) {
        const long long chunks = (long long)N * 4;
        const long long stride = (long long)gridDim.x * 256;
        for (long long i = (long long)blockIdx.x * 256 + tid; i < chunks; i += stride) {
            const long long r = i >> 2;
            const int cb = (int)(i & 3) * 8;
            uint4 v = ((const uint4*)g_y)[i];
            float2 f0 = __half22float2(*(__half2*)&v.x);
            float2 f1 = __half22float2(*(__half2*)&v.y);
            float2 f2 = __half22float2(*(__half2*)&v.z);
            float2 f3 = __half22float2(*(__half2*)&v.w);
            float4 o0, o1;
            o0.x = f0.x * sc[cb + 0] + bi[cb + 0];
            o0.y = f0.y * sc[cb + 1] + bi[cb + 1];
            o0.z = f1.x * sc[cb + 2] + bi[cb + 2];
            o0.w = f1.y * sc[cb + 3] + bi[cb + 3];
            o1.x = f2.x * sc[cb + 4] + bi[cb + 4];
            o1.y = f2.y * sc[cb + 5] + bi[cb + 5];
            o1.z = f3.x * sc[cb + 6] + bi[cb + 6];
            o1.w = f3.y * sc[cb + 7] + bi[cb + 7];
            float4* op = (float4*)(out + r * 32 + cb);
            op[0] = o0;
            op[1] = o1;
        }
    } else {
        const long long total4 = (long long)N * 8;
        const long long stride = (long long)gridDim.x * 256;
        for (long long i = (long long)blockIdx.x * 256 + tid; i < total4; i += stride) {
            int cb = ((int)i & 7) * 4;
            float4 v = ((float4*)out)[i];
            v.x = v.x * sc[cb + 0] + bi[cb + 0];
            v.y = v.y * sc[cb + 1] + bi[cb + 1];
            v.z = v.z * sc[cb + 2] + bi[cb + 2];
            v.w = v.w * sc[cb + 3] + bi[cb + 3];
            ((float4*)out)[i] = v;
        }
    }
}

// ---------------------------------------------------------------------------
extern "C" void kernel_launch(void* const* d_in, const int* in_sizes, int n_in,
                              void* d_out, int out_size) {
    const float* feat  = (const float*)d_in[0];
    const float* wt    = (const float*)d_in[1];
    const float* gamma = (const float*)d_in[2];
    const float* beta  = (const float*)d_in[3];
    const int*   nidx  = (const int*)d_in[4];
    const void*  nmask = d_in[5];
    float* out = (float*)d_out;

    const int N = in_sizes[0] / 32;
    const int use16 = (N <= Y_CAP_VOX) ? 1 : 0;

    k_prep<<<1, 256>>>((const unsigned int*)nmask, wt);   // launch 1

    const int tiles = (N + 255) / 256;
    const int ctas  = (tiles < PERSIST_CTAS) ? tiles : PERSIST_CTAS;
    k_conv<<<ctas, 256>>>(feat, nidx, nmask, out, gamma, beta,
                          N, tiles, use16, ctas);          // launch 2
}